// round 6
// baseline (speedup 1.0000x reference)
#include <cuda_runtime.h>
#include <math.h>

#define DD 128
#define VOL (DD*DD*DD)
#define NSL 16
#define NPIX (NSL*DD*DD)
#define CG_ITER 10

#define SC_RR   0
#define SC_PAP  16
#define SC_DUMP 31

// scatter kernel config: 64 threads, each owns a 2x2 pixel quad, 7x7x6 private tile
#define TPB2 64
#define PCX 7
#define PCY 7
#define PCZ 6
#define PC2 (PCX*PCY*PCZ)          // 294
#define HEAVY_SMEM (PC2 * TPB2 * 4) // 75264 B

__device__ float g_x[VOL];
__device__ float g_r[VOL];
__device__ float g_p[VOL];
__device__ float g_Ap[VOL];
__device__ float g_b[VOL];
__device__ float g_sl[NPIX];
__device__ float g_scal[32];

// ---------------- block reduction (sum) ----------------
__device__ __forceinline__ float block_sum(float v) {
    __shared__ float sh[8];
    int lane = threadIdx.x & 31, wid = threadIdx.x >> 5;
#pragma unroll
    for (int o = 16; o > 0; o >>= 1) v += __shfl_down_sync(0xffffffffu, v, o);
    if (lane == 0) sh[wid] = v;
    __syncthreads();
    if (wid == 0) {
        v = (lane < (blockDim.x >> 5)) ? sh[lane] : 0.f;
#pragma unroll
        for (int o = 4; o > 0; o >>= 1) v += __shfl_down_sync(0xffffffffu, v, o);
    }
    return v;  // valid in thread 0
}

// ---------------- small vector kernels ----------------
__global__ void k_init(float4* __restrict__ b4, float4* __restrict__ ap4) {
    int i = blockIdx.x * blockDim.x + threadIdx.x;
    float4 z = make_float4(0.f, 0.f, 0.f, 0.f);
    if (i < VOL / 4) { b4[i] = z; ap4[i] = z; }
    if (i < 32) g_scal[i] = 0.f;
}

__global__ void k_rp0(float4* __restrict__ r4, float4* __restrict__ p4,
                      const float4* __restrict__ b4, float4* __restrict__ ap4) {
    int i = blockIdx.x * blockDim.x + threadIdx.x;
    float s = 0.f;
    if (i < VOL / 4) {
        float4 b = b4[i], a = ap4[i];
        float4 v = make_float4(b.x - a.x, b.y - a.y, b.z - a.z, b.w - a.w);
        r4[i] = v; p4[i] = v;
        ap4[i] = make_float4(0.f, 0.f, 0.f, 0.f);
        s = v.x * v.x + v.y * v.y + v.z * v.z + v.w * v.w;
    }
    s = block_sum(s);
    if (threadIdx.x == 0) atomicAdd(&g_scal[SC_RR + 0], s);
}

__global__ void k_xr(const float4* __restrict__ xin4, float4* __restrict__ xout4,
                     float4* __restrict__ r4, const float4* __restrict__ p4,
                     const float4* __restrict__ ap4, int it) {
    int i = blockIdx.x * blockDim.x + threadIdx.x;
    float s = 0.f;
    if (i < VOL / 4) {
        float a = g_scal[SC_RR + it] / g_scal[SC_PAP + it];
        float4 x = xin4[i], p = p4[i], ap = ap4[i], r = r4[i];
        x.x = fmaf(a, p.x, x.x); x.y = fmaf(a, p.y, x.y);
        x.z = fmaf(a, p.z, x.z); x.w = fmaf(a, p.w, x.w);
        r.x = fmaf(-a, ap.x, r.x); r.y = fmaf(-a, ap.y, r.y);
        r.z = fmaf(-a, ap.z, r.z); r.w = fmaf(-a, ap.w, r.w);
        xout4[i] = x; r4[i] = r;
        s = r.x * r.x + r.y * r.y + r.z * r.z + r.w * r.w;
    }
    s = block_sum(s);
    if (threadIdx.x == 0) atomicAdd(&g_scal[SC_RR + it + 1], s);
}

__global__ void k_updp(float4* __restrict__ p4, const float4* __restrict__ r4,
                       float4* __restrict__ ap4, int it) {
    int i = blockIdx.x * blockDim.x + threadIdx.x;
    if (i < VOL / 4) {
        float b = g_scal[SC_RR + it + 1] / g_scal[SC_RR + it];
        float4 p = p4[i], r = r4[i];
        p.x = fmaf(b, p.x, r.x); p.y = fmaf(b, p.y, r.y);
        p.z = fmaf(b, p.z, r.z); p.w = fmaf(b, p.w, r.w);
        p4[i] = p;
        ap4[i] = make_float4(0.f, 0.f, 0.f, 0.f);
    }
}

__global__ void k_relu(float4* __restrict__ o4, const float4* __restrict__ x4) {
    int i = blockIdx.x * blockDim.x + threadIdx.x;
    if (i < VOL / 4) {
        float4 x = x4[i];
        o4[i] = make_float4(fmaxf(x.x, 0.f), fmaxf(x.y, 0.f),
                            fmaxf(x.z, 0.f), fmaxf(x.w, 0.f));
    }
}

// ---------------- gathers ----------------
__device__ __forceinline__ float tri_gather_safe(const float* __restrict__ vol,
                                                 float x, float y, float z) {
    float x0f = floorf(x), y0f = floorf(y), z0f = floorf(z);
    float fx = x - x0f, fy = y - y0f, fz = z - z0f;
    int x0 = (int)x0f, y0 = (int)y0f, z0 = (int)z0f;
    float v = 0.f;
#pragma unroll
    for (int dz = 0; dz < 2; dz++) {
        int zi = z0 + dz;
        if (zi < 0 || zi >= DD) continue;
        float wz = dz ? fz : 1.f - fz;
#pragma unroll
        for (int dy = 0; dy < 2; dy++) {
            int yi = y0 + dy;
            if (yi < 0 || yi >= DD) continue;
            float wzy = wz * (dy ? fy : 1.f - fy);
            int base = (zi << 14) + (yi << 7);
#pragma unroll
            for (int dx = 0; dx < 2; dx++) {
                int xi = x0 + dx;
                if (xi < 0 || xi >= DD) continue;
                v = fmaf(wzy * (dx ? fx : 1.f - fx), __ldg(vol + base + xi), v);
            }
        }
    }
    return v;
}

__device__ __forceinline__ float tri_gather_fast(const float* __restrict__ vol,
                                                 float x, float y, float z) {
    float x0f = floorf(x), y0f = floorf(y), z0f = floorf(z);
    float fx = x - x0f, fy = y - y0f, fz = z - z0f;
    int idx = (((int)z0f) << 14) + (((int)y0f) << 7) + (int)x0f;
    const float* p = vol + idx;
    float v000 = __ldg(p),         v001 = __ldg(p + 1);
    float v010 = __ldg(p + 128),   v011 = __ldg(p + 129);
    float v100 = __ldg(p + 16384), v101 = __ldg(p + 16385);
    float v110 = __ldg(p + 16512), v111 = __ldg(p + 16513);
    float c00 = fmaf(fx, v001 - v000, v000);
    float c01 = fmaf(fx, v011 - v010, v010);
    float c10 = fmaf(fx, v101 - v100, v100);
    float c11 = fmaf(fx, v111 - v110, v110);
    float c0 = fmaf(fy, c01 - c00, c00);
    float c1 = fmaf(fy, c11 - c10, c10);
    return fmaf(fz, c1 - c0, c0);
}

// direct global-atomic scatter (fallback only)
__device__ __forceinline__ void tri_scatter_safe(float* __restrict__ vol,
                                                 float x, float y, float z, float wv) {
    float x0f = floorf(x), y0f = floorf(y), z0f = floorf(z);
    float fx = x - x0f, fy = y - y0f, fz = z - z0f;
    int x0 = (int)x0f, y0 = (int)y0f, z0 = (int)z0f;
#pragma unroll
    for (int dz = 0; dz < 2; dz++) {
        int zi = z0 + dz;
        if (zi < 0 || zi >= DD) continue;
        float wz = (dz ? fz : 1.f - fz) * wv;
#pragma unroll
        for (int dy = 0; dy < 2; dy++) {
            int yi = y0 + dy;
            if (yi < 0 || yi >= DD) continue;
            float wzy = wz * (dy ? fy : 1.f - fy);
            int base = (zi << 14) + (yi << 7);
#pragma unroll
            for (int dx = 0; dx < 2; dx++) {
                int xi = x0 + dx;
                if (xi < 0 || xi >= DD) continue;
                atomicAdd(vol + base + xi, wzy * (dx ? fx : 1.f - fx));
            }
        }
    }
}

// private-SMEM scatter into 7x7x6 quad tile (stride TPB2)
__device__ __forceinline__ void tri_scatter_priv(float* __restrict__ priv,
                                                 int ox, int oy, int oz,
                                                 float x, float y, float z, float wv) {
    float x0f = floorf(x), y0f = floorf(y), z0f = floorf(z);
    float fx = x - x0f, fy = y - y0f, fz = z - z0f;
    int c = (((int)z0f - oz) * PCY + ((int)y0f - oy)) * PCX + ((int)x0f - ox);
    float wz1 = fz * wv, wz0 = wv - wz1;
    float w01 = fy * wz0, w00 = wz0 - w01;
    float w11 = fy * wz1, w10 = wz1 - w11;
    float t;
    t = fx * w00; priv[c * TPB2]        += w00 - t; priv[(c + 1) * TPB2]  += t;
    t = fx * w01; priv[(c + PCX) * TPB2]     += w01 - t; priv[(c + PCX + 1) * TPB2]  += t;
    t = fx * w10; priv[(c + PCX*PCY) * TPB2] += w10 - t; priv[(c + PCX*PCY + 1) * TPB2] += t;
    t = fx * w11; priv[(c + PCX*PCY + PCX) * TPB2] += w11 - t;
                  priv[(c + PCX*PCY + PCX + 1) * TPB2] += t;
}

// ---------------- geometry ----------------
struct Geo {
    float qx, qy, qz;
    int status;  // 0 reject, 1 interior, 2 boundary
};

__device__ __forceinline__ Geo pixel_geo(const float* sT, float rx, float ry, float rz,
                                         int w, int h) {
    Geo g;
    float u = (w - 63.5f) * 1.5f;
    float v = (h - 63.5f) * 1.5f;
    g.qx = sT[0] * u + sT[1] * v + sT[3]  + 63.5f;
    g.qy = sT[4] * u + sT[5] * v + sT[7]  + 63.5f;
    g.qz = sT[8] * u + sT[9] * v + sT[11] + 63.5f;
    bool rej = (g.qx + rx < -1.f) | (g.qx - rx >= 128.f) |
               (g.qy + ry < -1.f) | (g.qy - ry >= 128.f) |
               (g.qz + rz < -1.f) | (g.qz - rz >= 128.f);
    bool inter = (g.qx - rx >= 0.f) & (g.qx + rx < 127.f) &
                 (g.qy - ry >= 0.f) & (g.qy + ry < 127.f) &
                 (g.qz - rz >= 0.f) & (g.qz + rz < 127.f);
    g.status = rej ? 0 : (inter ? 1 : 2);
    return g;
}

// ---------------- k_A: forward gather, writes slice values + pAp ----------------
__global__ void __launch_bounds__(256)
k_A(const float* __restrict__ th, const float* __restrict__ src,
    const float* __restrict__ psf, float* __restrict__ sl,
    float* __restrict__ pap) {
    __shared__ float sp[27];
    __shared__ float sT[12];
    int tid = threadIdx.x;
    int b = blockIdx.x;
    int n = b >> 6;                       // 64 blocks per slice
    if (tid < 27) sp[tid] = psf[tid];
    if (tid < 12) sT[tid] = th[n * 12 + tid];
    __syncthreads();
    int tile = b & 63;                    // 8x8 tiles of 16x16
    int w = ((tile & 7) << 4) + (tid & 15);
    int h = ((tile >> 3) << 4) + (tid >> 4);

    float r00 = sT[0], r01 = sT[1], r02 = sT[2];
    float r10 = sT[4], r11 = sT[5], r12 = sT[6];
    float r20 = sT[8], r21 = sT[9], r22 = sT[10];
    float rx = fabsf(r00) + fabsf(r01) + fabsf(r02);
    float ry = fabsf(r10) + fabsf(r11) + fabsf(r12);
    float rz = fabsf(r20) + fabsf(r21) + fabsf(r22);
    Geo g = pixel_geo(sT, rx, ry, rz, w, h);

    float acc = 0.f;
    if (g.status == 1) {
        int k = 0;
        for (int iz = -1; iz <= 1; iz++) {
            float zx = g.qx + iz * r02, zy = g.qy + iz * r12, zz = g.qz + iz * r22;
            for (int iy = -1; iy <= 1; iy++) {
                float yx = zx + iy * r01, yy = zy + iy * r11, yz = zz + iy * r21;
                for (int ix = -1; ix <= 1; ix++, k++)
                    acc = fmaf(sp[k], tri_gather_fast(src, yx + ix * r00,
                                                      yy + ix * r10, yz + ix * r20), acc);
            }
        }
    } else if (g.status == 2) {
        int k = 0;
        for (int iz = -1; iz <= 1; iz++) {
            float zx = g.qx + iz * r02, zy = g.qy + iz * r12, zz = g.qz + iz * r22;
            for (int iy = -1; iy <= 1; iy++) {
                float yx = zx + iy * r01, yy = zy + iy * r11, yz = zz + iy * r21;
                for (int ix = -1; ix <= 1; ix++, k++)
                    acc = fmaf(sp[k], tri_gather_safe(src, yx + ix * r00,
                                                      yy + ix * r10, yz + ix * r20), acc);
            }
        }
    }
    sl[(n << 14) + (h << 7) + w] = acc;
    float s = block_sum(acc * acc);
    if (tid == 0) atomicAdd(pap, s);
}

// ---------------- k_Scat: adjoint scatter of slice values (2x2 quads) ----------------
__global__ void __launch_bounds__(TPB2)
k_Scat(const float* __restrict__ th, const float* __restrict__ sl,
       const float* __restrict__ psf, float* __restrict__ dst) {
    extern __shared__ float scr[];
    __shared__ float sp[27];
    __shared__ float sT[12];
    int tid = threadIdx.x;
    int b = blockIdx.x;
    int n = b >> 6;                       // 64 blocks per slice (16x16 pixels each)
    if (tid < 27) sp[tid] = psf[tid];
    if (tid < 12) sT[tid] = th[n * 12 + tid];
    __syncthreads();
    int tile = b & 63;
    int w0 = ((tile & 7) << 4) + ((tid & 7) << 1);
    int h0 = ((tile >> 3) << 4) + ((tid >> 3) << 1);

    float r00 = sT[0], r01 = sT[1], r02 = sT[2];
    float r10 = sT[4], r11 = sT[5], r12 = sT[6];
    float r20 = sT[8], r21 = sT[9], r22 = sT[10];
    float rx = fabsf(r00) + fabsf(r01) + fabsf(r02);
    float ry = fabsf(r10) + fabsf(r11) + fabsf(r12);
    float rz = fabsf(r20) + fabsf(r21) + fabsf(r22);

    Geo ge[4];
    float sv[4];
    int any = 0;
    float mnx = 1e9f, mxx = -1e9f, mny = 1e9f, mxy = -1e9f, mnz = 1e9f, mxz = -1e9f;
#pragma unroll
    for (int q = 0; q < 4; q++) {
        int w = w0 + (q & 1), h = h0 + (q >> 1);
        ge[q] = pixel_geo(sT, rx, ry, rz, w, h);
        sv[q] = __ldg(sl + (n << 14) + (h << 7) + w);
        if (ge[q].status == 0 || sv[q] == 0.f) ge[q].status = 0;
        else any = 1;
        mnx = fminf(mnx, ge[q].qx); mxx = fmaxf(mxx, ge[q].qx);
        mny = fminf(mny, ge[q].qy); mxy = fmaxf(mxy, ge[q].qy);
        mnz = fminf(mnz, ge[q].qz); mxz = fmaxf(mxz, ge[q].qz);
    }
    if (!any) return;

    // quad footprint fit check (7x7x6 cells)
    bool fits = ((mxx - mnx + 2.f * rx) < 4.98f) &
                ((mxy - mny + 2.f * ry) < 4.98f) &
                ((mxz - mnz + 2.f * rz) < 3.98f) &
                (rx < 1.49f) & (ry < 1.49f) & (rz < 1.49f);

    if (!fits) {  // never expected; exact fallback
#pragma unroll
        for (int q = 0; q < 4; q++) {
            if (ge[q].status == 0) continue;
            float s = sv[q];
            int k = 0;
            for (int iz = -1; iz <= 1; iz++) {
                float zx = ge[q].qx + iz * r02, zy = ge[q].qy + iz * r12, zz = ge[q].qz + iz * r22;
                for (int iy = -1; iy <= 1; iy++) {
                    float yx = zx + iy * r01, yy = zy + iy * r11, yz = zz + iy * r21;
                    for (int ix = -1; ix <= 1; ix++, k++)
                        tri_scatter_safe(dst, yx + ix * r00, yy + ix * r10,
                                         yz + ix * r20, s * sp[k]);
                }
            }
        }
        return;
    }

    float* priv = scr + tid;
#pragma unroll 6
    for (int c = 0; c < PC2; c++) priv[c * TPB2] = 0.f;
    int ox = (int)floorf(mnx - rx);
    int oy = (int)floorf(mny - ry);
    int oz = (int)floorf(mnz - rz);

#pragma unroll
    for (int q = 0; q < 4; q++) {
        if (ge[q].status == 0) continue;
        float s = sv[q];
        int k = 0;
        for (int iz = -1; iz <= 1; iz++) {
            float zx = ge[q].qx + iz * r02, zy = ge[q].qy + iz * r12, zz = ge[q].qz + iz * r22;
            for (int iy = -1; iy <= 1; iy++) {
                float yx = zx + iy * r01, yy = zy + iy * r11, yz = zz + iy * r21;
                for (int ix = -1; ix <= 1; ix++, k++)
                    tri_scatter_priv(priv, ox, oy, oz, yx + ix * r00,
                                     yy + ix * r10, yz + ix * r20, s * sp[k]);
            }
        }
    }

    // flush
#pragma unroll 6
    for (int c = 0; c < PC2; c++) {
        float v = priv[c * TPB2];
        if (v != 0.f) {
            int x = ox + (c % PCX), y = oy + ((c / PCX) % PCY), z = oz + (c / (PCX * PCY));
            if ((unsigned)x < DD && (unsigned)y < DD && (unsigned)z < DD)
                atomicAdd(dst + (z << 14) + (y << 7) + x, v);
        }
    }
}

// ---------------- host driver ----------------
extern "C" void kernel_launch(void* const* d_in, const int* in_sizes, int n_in,
                              void* d_out, int out_size) {
    const float *theta = nullptr, *slices = nullptr, *vol0 = nullptr, *psf = nullptr;
    for (int i = 0; i < n_in; i++) {
        switch (in_sizes[i]) {
            case 192:   theta  = (const float*)d_in[i]; break;
            case NPIX:  slices = (const float*)d_in[i]; break;
            case VOL:   vol0   = (const float*)d_in[i]; break;
            case 27:    psf    = (const float*)d_in[i]; break;
        }
    }

    float *px, *pr, *pp, *pap, *pb, *psl, *pscal;
    cudaGetSymbolAddress((void**)&px,    g_x);
    cudaGetSymbolAddress((void**)&pr,    g_r);
    cudaGetSymbolAddress((void**)&pp,    g_p);
    cudaGetSymbolAddress((void**)&pap,   g_Ap);
    cudaGetSymbolAddress((void**)&pb,    g_b);
    cudaGetSymbolAddress((void**)&psl,   g_sl);
    cudaGetSymbolAddress((void**)&pscal, g_scal);

    cudaFuncSetAttribute(k_Scat, cudaFuncAttributeMaxDynamicSharedMemorySize, HEAVY_SMEM);

    const int V4B = (VOL / 4) / 256;   // 2048
    const int GB  = NPIX / 256;        // 1024 gather blocks
    const int SB  = NPIX / (TPB2 * 4); // 1024 scatter blocks

    k_init<<<V4B, 256>>>((float4*)pb, (float4*)pap);
    // b = At(slices)
    k_Scat<<<SB, TPB2, HEAVY_SMEM>>>(theta, slices, psf, pb);
    // Ap = AtA(x0)
    k_A<<<GB, 256>>>(theta, vol0, psf, psl, pscal + SC_DUMP);
    k_Scat<<<SB, TPB2, HEAVY_SMEM>>>(theta, psl, psf, pap);
    k_rp0<<<V4B, 256>>>((float4*)pr, (float4*)pp, (float4*)pb, (float4*)pap);

    for (int it = 0; it < CG_ITER; it++) {
        k_A<<<GB, 256>>>(theta, pp, psf, psl, pscal + SC_PAP + it);
        k_Scat<<<SB, TPB2, HEAVY_SMEM>>>(theta, psl, psf, pap);
        const float* xin = (it == 0) ? vol0 : px;
        k_xr<<<V4B, 256>>>((const float4*)xin, (float4*)px, (float4*)pr,
                           (const float4*)pp, (const float4*)pap, it);
        k_updp<<<V4B, 256>>>((float4*)pp, (const float4*)pr, (float4*)pap, it);
    }

    k_relu<<<V4B, 256>>>((float4*)d_out, (const float4*)px);
    (void)out_size;
}

// round 7
// speedup vs baseline: 1.3426x; 1.3426x over previous
#include <cuda_runtime.h>
#include <math.h>

#define DD 128
#define VOL (DD*DD*DD)
#define NSL 16
#define NPIX (NSL*DD*DD)
#define CG_ITER 10

#define SC_RR   0
#define SC_PAP  16
#define SC_DUMP 31

#define TPB 128
#define PCX 4
#define PCY 5
#define PCZ 5
#define PCELLS (PCX*PCY*PCZ)            // 100
#define HEAVY_SMEM (PCELLS * TPB * 4)   // 51200 B -> 4 CTAs/SM

__device__ float g_x[VOL];
__device__ float g_r[VOL];
__device__ float g_p[VOL];
__device__ float g_Ap[VOL];
__device__ float g_b[VOL];
__device__ float g_scal[32];

// ---------------- block reduction (sum) ----------------
__device__ __forceinline__ float block_sum(float v) {
    __shared__ float sh[8];
    int lane = threadIdx.x & 31, wid = threadIdx.x >> 5;
#pragma unroll
    for (int o = 16; o > 0; o >>= 1) v += __shfl_down_sync(0xffffffffu, v, o);
    if (lane == 0) sh[wid] = v;
    __syncthreads();
    if (wid == 0) {
        v = (lane < (blockDim.x >> 5)) ? sh[lane] : 0.f;
#pragma unroll
        for (int o = 4; o > 0; o >>= 1) v += __shfl_down_sync(0xffffffffu, v, o);
    }
    return v;
}

// ---------------- small vector kernels ----------------
__global__ void k_init(float4* __restrict__ b4, float4* __restrict__ ap4) {
    int i = blockIdx.x * blockDim.x + threadIdx.x;
    float4 z = make_float4(0.f, 0.f, 0.f, 0.f);
    if (i < VOL / 4) { b4[i] = z; ap4[i] = z; }
    if (i < 32) g_scal[i] = 0.f;
}

__global__ void k_rp0(float4* __restrict__ r4, float4* __restrict__ p4,
                      const float4* __restrict__ b4, float4* __restrict__ ap4) {
    int i = blockIdx.x * blockDim.x + threadIdx.x;
    float s = 0.f;
    if (i < VOL / 4) {
        float4 b = b4[i], a = ap4[i];
        float4 v = make_float4(b.x - a.x, b.y - a.y, b.z - a.z, b.w - a.w);
        r4[i] = v; p4[i] = v;
        ap4[i] = make_float4(0.f, 0.f, 0.f, 0.f);
        s = v.x * v.x + v.y * v.y + v.z * v.z + v.w * v.w;
    }
    s = block_sum(s);
    if (threadIdx.x == 0) atomicAdd(&g_scal[SC_RR + 0], s);
}

__global__ void k_xr(const float4* __restrict__ xin4, float4* __restrict__ xout4,
                     float4* __restrict__ r4, const float4* __restrict__ p4,
                     const float4* __restrict__ ap4, int it) {
    int i = blockIdx.x * blockDim.x + threadIdx.x;
    float s = 0.f;
    if (i < VOL / 4) {
        float a = g_scal[SC_RR + it] / g_scal[SC_PAP + it];
        float4 x = xin4[i], p = p4[i], ap = ap4[i], r = r4[i];
        x.x = fmaf(a, p.x, x.x); x.y = fmaf(a, p.y, x.y);
        x.z = fmaf(a, p.z, x.z); x.w = fmaf(a, p.w, x.w);
        r.x = fmaf(-a, ap.x, r.x); r.y = fmaf(-a, ap.y, r.y);
        r.z = fmaf(-a, ap.z, r.z); r.w = fmaf(-a, ap.w, r.w);
        xout4[i] = x; r4[i] = r;
        s = r.x * r.x + r.y * r.y + r.z * r.z + r.w * r.w;
    }
    s = block_sum(s);
    if (threadIdx.x == 0) atomicAdd(&g_scal[SC_RR + it + 1], s);
}

__global__ void k_updp(float4* __restrict__ p4, const float4* __restrict__ r4,
                       float4* __restrict__ ap4, int it) {
    int i = blockIdx.x * blockDim.x + threadIdx.x;
    if (i < VOL / 4) {
        float b = g_scal[SC_RR + it + 1] / g_scal[SC_RR + it];
        float4 p = p4[i], r = r4[i];
        p.x = fmaf(b, p.x, r.x); p.y = fmaf(b, p.y, r.y);
        p.z = fmaf(b, p.z, r.z); p.w = fmaf(b, p.w, r.w);
        p4[i] = p;
        ap4[i] = make_float4(0.f, 0.f, 0.f, 0.f);
    }
}

__global__ void k_relu(float4* __restrict__ o4, const float4* __restrict__ x4) {
    int i = blockIdx.x * blockDim.x + threadIdx.x;
    if (i < VOL / 4) {
        float4 x = x4[i];
        o4[i] = make_float4(fmaxf(x.x, 0.f), fmaxf(x.y, 0.f),
                            fmaxf(x.z, 0.f), fmaxf(x.w, 0.f));
    }
}

// ---------------- gathers ----------------
__device__ __forceinline__ float tri_gather_safe(const float* __restrict__ vol,
                                                 float x, float y, float z) {
    float x0f = floorf(x), y0f = floorf(y), z0f = floorf(z);
    float fx = x - x0f, fy = y - y0f, fz = z - z0f;
    int x0 = (int)x0f, y0 = (int)y0f, z0 = (int)z0f;
    float v = 0.f;
#pragma unroll
    for (int dz = 0; dz < 2; dz++) {
        int zi = z0 + dz;
        if (zi < 0 || zi >= DD) continue;
        float wz = dz ? fz : 1.f - fz;
#pragma unroll
        for (int dy = 0; dy < 2; dy++) {
            int yi = y0 + dy;
            if (yi < 0 || yi >= DD) continue;
            float wzy = wz * (dy ? fy : 1.f - fy);
            int base = (zi << 14) + (yi << 7);
#pragma unroll
            for (int dx = 0; dx < 2; dx++) {
                int xi = x0 + dx;
                if (xi < 0 || xi >= DD) continue;
                v = fmaf(wzy * (dx ? fx : 1.f - fx), __ldg(vol + base + xi), v);
            }
        }
    }
    return v;
}

__device__ __forceinline__ float tri_gather_fast(const float* __restrict__ vol,
                                                 float x, float y, float z) {
    float x0f = floorf(x), y0f = floorf(y), z0f = floorf(z);
    float fx = x - x0f, fy = y - y0f, fz = z - z0f;
    int idx = (((int)z0f) << 14) + (((int)y0f) << 7) + (int)x0f;
    const float* p = vol + idx;
    float v000 = __ldg(p),         v001 = __ldg(p + 1);
    float v010 = __ldg(p + 128),   v011 = __ldg(p + 129);
    float v100 = __ldg(p + 16384), v101 = __ldg(p + 16385);
    float v110 = __ldg(p + 16512), v111 = __ldg(p + 16513);
    float c00 = fmaf(fx, v001 - v000, v000);
    float c01 = fmaf(fx, v011 - v010, v010);
    float c10 = fmaf(fx, v101 - v100, v100);
    float c11 = fmaf(fx, v111 - v110, v110);
    float c0 = fmaf(fy, c01 - c00, c00);
    float c1 = fmaf(fy, c11 - c10, c10);
    return fmaf(fz, c1 - c0, c0);
}

// direct global-atomic scatter (boundary / fallback)
__device__ __forceinline__ void tri_scatter_safe(float* __restrict__ vol,
                                                 float x, float y, float z, float wv) {
    float x0f = floorf(x), y0f = floorf(y), z0f = floorf(z);
    float fx = x - x0f, fy = y - y0f, fz = z - z0f;
    int x0 = (int)x0f, y0 = (int)y0f, z0 = (int)z0f;
#pragma unroll
    for (int dz = 0; dz < 2; dz++) {
        int zi = z0 + dz;
        if (zi < 0 || zi >= DD) continue;
        float wz = (dz ? fz : 1.f - fz) * wv;
#pragma unroll
        for (int dy = 0; dy < 2; dy++) {
            int yi = y0 + dy;
            if (yi < 0 || yi >= DD) continue;
            float wzy = wz * (dy ? fy : 1.f - fy);
            int base = (zi << 14) + (yi << 7);
#pragma unroll
            for (int dx = 0; dx < 2; dx++) {
                int xi = x0 + dx;
                if (xi < 0 || xi >= DD) continue;
                atomicAdd(vol + base + xi, wzy * (dx ? fx : 1.f - fx));
            }
        }
    }
}

// ---------------- geometry ----------------
struct Geo {
    float qx, qy, qz;
    int status;  // 0 reject, 1 interior+fits (smem path), 2 safe-global path
};

__device__ __forceinline__ Geo pixel_geo(const float* sT, float rx, float ry, float rz,
                                         int w, int h) {
    Geo g;
    float u = (w - 63.5f) * 1.5f;
    float v = (h - 63.5f) * 1.5f;
    g.qx = sT[0] * u + sT[1] * v + sT[3]  + 63.5f;
    g.qy = sT[4] * u + sT[5] * v + sT[7]  + 63.5f;
    g.qz = sT[8] * u + sT[9] * v + sT[11] + 63.5f;
    bool rej = (g.qx + rx < -1.f) | (g.qx - rx >= 128.f) |
               (g.qy + ry < -1.f) | (g.qy - ry >= 128.f) |
               (g.qz + rz < -1.f) | (g.qz - rz >= 128.f);
    bool inter = (g.qx - rx >= 0.f) & (g.qx + rx < 127.f) &
                 (g.qy - ry >= 0.f) & (g.qy + ry < 127.f) &
                 (g.qz - rz >= 0.f) & (g.qz + rz < 127.f) &
                 (rx < 1.49f) & (ry < 1.49f) & (rz < 1.49f);
    g.status = rej ? 0 : (inter ? 1 : 2);
    return g;
}

// ---------------- interior smem-privatized scatter of one pixel ----------------
// val: scalar to scatter; geometry interior-guaranteed (all corners in-bounds).
__device__ __forceinline__ void scatter_interior(
    float* __restrict__ priv, float* __restrict__ dst, const float* __restrict__ sp,
    float qx, float qy, float qz,
    float r00, float r01, float r02, float r10, float r11, float r12,
    float r20, float r21, float r22, float rx, float ry, float rz, float val) {

    int ox = (int)floorf(qx - rx);
    int oy = (int)floorf(qy - ry);
    int oz = (int)floorf(qz - rz);
    int ey = (int)floorf(qy + ry) + 2 - oy;   // <= 5
    int ez = (int)floorf(qz + rz) + 2 - oz;   // <= 5

    // zero only the used footprint (x always 4-wide)
    for (int cz = 0; cz < ez; cz++) {
        int zb = cz * (PCY * PCX);
        for (int cy = 0; cy < ey; cy++) {
            int cb = zb + cy * PCX;
            priv[(cb + 0) * TPB] = 0.f;
            priv[(cb + 1) * TPB] = 0.f;
            priv[(cb + 2) * TPB] = 0.f;
            priv[(cb + 3) * TPB] = 0.f;
        }
    }

    int k = 0;
#pragma unroll
    for (int iz = -1; iz <= 1; iz++) {
        float zx = qx + iz * r02, zy = qy + iz * r12, zz = qz + iz * r22;
#pragma unroll
        for (int iy = -1; iy <= 1; iy++) {
            float yx = zx + iy * r01, yy = zy + iy * r11, yz = zz + iy * r21;
#pragma unroll
            for (int ix = -1; ix <= 1; ix++, k++) {
                float x = yx + ix * r00, y = yy + ix * r10, z = yz + ix * r20;
                float wv = val * sp[k];
                float x0f = floorf(x), y0f = floorf(y), z0f = floorf(z);
                float fx = x - x0f, fy = y - y0f, fz = z - z0f;
                int x0 = (int)x0f, y0 = (int)y0f, z0 = (int)z0f;
                int cx = x0 - ox, cy = y0 - oy, cz = z0 - oz;
                float wz1 = fz * wv, wz0 = wv - wz1;
                float w01 = fy * wz0, w00 = wz0 - w01;
                float w11 = fy * wz1, w10 = wz1 - w11;
                int cb = (cz * PCY + cy) * PCX + cx;
                float t00 = fx * w00, t01 = fx * w01, t10 = fx * w10, t11 = fx * w11;
                priv[cb * TPB]                     += w00 - t00;
                priv[(cb + PCX) * TPB]             += w01 - t01;
                priv[(cb + PCX*PCY) * TPB]         += w10 - t10;
                priv[(cb + PCX*PCY + PCX) * TPB]   += w11 - t11;
                if (cx < PCX - 1) {
                    priv[(cb + 1) * TPB]                   += t00;
                    priv[(cb + PCX + 1) * TPB]             += t01;
                    priv[(cb + PCX*PCY + 1) * TPB]         += t10;
                    priv[(cb + PCX*PCY + PCX + 1) * TPB]   += t11;
                } else {
                    // rare x-overflow: direct global atomics (in-bounds for interior)
                    int gi = (z0 << 14) + (y0 << 7) + x0 + 1;
                    atomicAdd(dst + gi,               t00);
                    atomicAdd(dst + gi + 128,         t01);
                    atomicAdd(dst + gi + 16384,       t10);
                    atomicAdd(dst + gi + 16512,       t11);
                }
            }
        }
    }

    // flush (interior: no bounds check needed)
    int gb = (oz << 14) + (oy << 7) + ox;
    for (int cz = 0; cz < ez; cz++) {
        int zb = cz * (PCY * PCX);
        int gz = gb + (cz << 14);
        for (int cy = 0; cy < ey; cy++) {
            int cb = zb + cy * PCX;
            int gy = gz + (cy << 7);
            float v0 = priv[(cb + 0) * TPB];
            float v1 = priv[(cb + 1) * TPB];
            float v2 = priv[(cb + 2) * TPB];
            float v3 = priv[(cb + 3) * TPB];
            if (v0 != 0.f) atomicAdd(dst + gy + 0, v0);
            if (v1 != 0.f) atomicAdd(dst + gy + 1, v1);
            if (v2 != 0.f) atomicAdd(dst + gy + 2, v2);
            if (v3 != 0.f) atomicAdd(dst + gy + 3, v3);
        }
    }
}

// safe scatter over all taps (boundary pixels)
__device__ __forceinline__ void scatter_safe_all(
    float* __restrict__ dst, const float* __restrict__ sp,
    float qx, float qy, float qz,
    float r00, float r01, float r02, float r10, float r11, float r12,
    float r20, float r21, float r22, float val) {
    int k = 0;
#pragma unroll
    for (int iz = -1; iz <= 1; iz++) {
        float zx = qx + iz * r02, zy = qy + iz * r12, zz = qz + iz * r22;
#pragma unroll
        for (int iy = -1; iy <= 1; iy++) {
            float yx = zx + iy * r01, yy = zy + iy * r11, yz = zz + iy * r21;
#pragma unroll
            for (int ix = -1; ix <= 1; ix++, k++)
                tri_scatter_safe(dst, yx + ix * r00, yy + ix * r10,
                                 yz + ix * r20, val * sp[k]);
        }
    }
}

// ---------------- fused AtA ----------------
__global__ void __launch_bounds__(TPB)
k_AtA(const float* __restrict__ th, const float* __restrict__ src,
      const float* __restrict__ psf, float* __restrict__ dst,
      float* __restrict__ pap) {
    extern __shared__ float scr[];
    __shared__ float sp[27];
    __shared__ float sT[12];
    int tid = threadIdx.x;
    int b = blockIdx.x;
    int n = b >> 7;                      // 128 blocks per slice
    if (tid < 27) sp[tid] = psf[tid];
    if (tid < 12) sT[tid] = th[n * 12 + tid];
    __syncthreads();
    int tile = b & 127;                  // 8 x-tiles * 16 y-tiles of 16x8 px
    int w = ((tile & 7) << 4) + (tid & 15);
    int h = ((tile >> 3) << 3) + (tid >> 4);

    float r00 = sT[0], r01 = sT[1], r02 = sT[2];
    float r10 = sT[4], r11 = sT[5], r12 = sT[6];
    float r20 = sT[8], r21 = sT[9], r22 = sT[10];
    float rx = fabsf(r00) + fabsf(r01) + fabsf(r02);
    float ry = fabsf(r10) + fabsf(r11) + fabsf(r12);
    float rz = fabsf(r20) + fabsf(r21) + fabsf(r22);
    Geo g = pixel_geo(sT, rx, ry, rz, w, h);

    float acc = 0.f;
    if (g.status == 1) {
        int k = 0;
#pragma unroll
        for (int iz = -1; iz <= 1; iz++) {
            float zx = g.qx + iz * r02, zy = g.qy + iz * r12, zz = g.qz + iz * r22;
#pragma unroll
            for (int iy = -1; iy <= 1; iy++) {
                float yx = zx + iy * r01, yy = zy + iy * r11, yz = zz + iy * r21;
#pragma unroll
                for (int ix = -1; ix <= 1; ix++, k++)
                    acc = fmaf(sp[k], tri_gather_fast(src, yx + ix * r00,
                                                      yy + ix * r10, yz + ix * r20), acc);
            }
        }
    } else if (g.status == 2) {
        int k = 0;
#pragma unroll
        for (int iz = -1; iz <= 1; iz++) {
            float zx = g.qx + iz * r02, zy = g.qy + iz * r12, zz = g.qz + iz * r22;
#pragma unroll
            for (int iy = -1; iy <= 1; iy++) {
                float yx = zx + iy * r01, yy = zy + iy * r11, yz = zz + iy * r21;
#pragma unroll
                for (int ix = -1; ix <= 1; ix++, k++)
                    acc = fmaf(sp[k], tri_gather_safe(src, yx + ix * r00,
                                                      yy + ix * r10, yz + ix * r20), acc);
            }
        }
    }
    float s = block_sum(acc * acc);
    if (tid == 0) atomicAdd(pap, s);

    if (acc == 0.f) return;
    if (g.status == 1)
        scatter_interior(scr + tid, dst, sp, g.qx, g.qy, g.qz,
                         r00, r01, r02, r10, r11, r12, r20, r21, r22,
                         rx, ry, rz, acc);
    else
        scatter_safe_all(dst, sp, g.qx, g.qy, g.qz,
                         r00, r01, r02, r10, r11, r12, r20, r21, r22, acc);
}

// ---------------- standalone At (b = At slices) ----------------
__global__ void __launch_bounds__(TPB)
k_At(const float* __restrict__ th, const float* __restrict__ sl,
     const float* __restrict__ psf, float* __restrict__ dst) {
    extern __shared__ float scr[];
    __shared__ float sp[27];
    __shared__ float sT[12];
    int tid = threadIdx.x;
    int b = blockIdx.x;
    int n = b >> 7;
    if (tid < 27) sp[tid] = psf[tid];
    if (tid < 12) sT[tid] = th[n * 12 + tid];
    __syncthreads();
    int tile = b & 127;
    int w = ((tile & 7) << 4) + (tid & 15);
    int h = ((tile >> 3) << 3) + (tid >> 4);

    float r00 = sT[0], r01 = sT[1], r02 = sT[2];
    float r10 = sT[4], r11 = sT[5], r12 = sT[6];
    float r20 = sT[8], r21 = sT[9], r22 = sT[10];
    float rx = fabsf(r00) + fabsf(r01) + fabsf(r02);
    float ry = fabsf(r10) + fabsf(r11) + fabsf(r12);
    float rz = fabsf(r20) + fabsf(r21) + fabsf(r22);
    Geo g = pixel_geo(sT, rx, ry, rz, w, h);
    if (g.status == 0) return;
    float s = __ldg(sl + (n << 14) + (h << 7) + w);
    if (s == 0.f) return;
    if (g.status == 1)
        scatter_interior(scr + tid, dst, sp, g.qx, g.qy, g.qz,
                         r00, r01, r02, r10, r11, r12, r20, r21, r22,
                         rx, ry, rz, s);
    else
        scatter_safe_all(dst, sp, g.qx, g.qy, g.qz,
                         r00, r01, r02, r10, r11, r12, r20, r21, r22, s);
}

// ---------------- host driver ----------------
extern "C" void kernel_launch(void* const* d_in, const int* in_sizes, int n_in,
                              void* d_out, int out_size) {
    const float *theta = nullptr, *slices = nullptr, *vol0 = nullptr, *psf = nullptr;
    for (int i = 0; i < n_in; i++) {
        switch (in_sizes[i]) {
            case 192:   theta  = (const float*)d_in[i]; break;
            case NPIX:  slices = (const float*)d_in[i]; break;
            case VOL:   vol0   = (const float*)d_in[i]; break;
            case 27:    psf    = (const float*)d_in[i]; break;
        }
    }

    float *px, *pr, *pp, *pap, *pb, *pscal;
    cudaGetSymbolAddress((void**)&px,    g_x);
    cudaGetSymbolAddress((void**)&pr,    g_r);
    cudaGetSymbolAddress((void**)&pp,    g_p);
    cudaGetSymbolAddress((void**)&pap,   g_Ap);
    cudaGetSymbolAddress((void**)&pb,    g_b);
    cudaGetSymbolAddress((void**)&pscal, g_scal);

    cudaFuncSetAttribute(k_AtA, cudaFuncAttributeMaxDynamicSharedMemorySize, HEAVY_SMEM);
    cudaFuncSetAttribute(k_At,  cudaFuncAttributeMaxDynamicSharedMemorySize, HEAVY_SMEM);

    const int V4B = (VOL / 4) / 256;   // 2048
    const int PB  = NPIX / TPB;        // 2048

    k_init<<<V4B, 256>>>((float4*)pb, (float4*)pap);
    k_At<<<PB, TPB, HEAVY_SMEM>>>(theta, slices, psf, pb);
    k_AtA<<<PB, TPB, HEAVY_SMEM>>>(theta, vol0, psf, pap, pscal + SC_DUMP);
    k_rp0<<<V4B, 256>>>((float4*)pr, (float4*)pp, (float4*)pb, (float4*)pap);

    for (int it = 0; it < CG_ITER; it++) {
        k_AtA<<<PB, TPB, HEAVY_SMEM>>>(theta, pp, psf, pap, pscal + SC_PAP + it);
        const float* xin = (it == 0) ? vol0 : px;
        k_xr<<<V4B, 256>>>((const float4*)xin, (float4*)px, (float4*)pr,
                           (const float4*)pp, (const float4*)pap, it);
        k_updp<<<V4B, 256>>>((float4*)pp, (const float4*)pr, (float4*)pap, it);
    }

    k_relu<<<V4B, 256>>>((float4*)d_out, (const float4*)px);
    (void)out_size;
}

// round 8
// speedup vs baseline: 1.4743x; 1.0980x over previous
#include <cuda_runtime.h>
#include <math.h>

#define DD 128
#define VOL (DD*DD*DD)
#define NSL 16
#define NPIX (NSL*DD*DD)
#define CG_ITER 10

#define SC_RR   0
#define SC_PAP  16
#define SC_DUMP 31

#define TPB 64             // threads per heavy block (8x8 pixel tile)
#define PCELLS 125         // 5x5x5 private footprint
#define HEAVY_SMEM (PCELLS * TPB * 4)   // 32000 B -> 7 CTAs/SM = 14 warps

__device__ float g_x[VOL];
__device__ float g_r[VOL];
__device__ float g_p[VOL];
__device__ float g_Ap[VOL];
__device__ float g_b[VOL];
__device__ float g_scal[32];

// ---------------- profiling alignment no-op ----------------
__global__ void k_nop() {}

// ---------------- block reduction (sum) ----------------
__device__ __forceinline__ float block_sum(float v) {
    __shared__ float sh[8];
    int lane = threadIdx.x & 31, wid = threadIdx.x >> 5;
#pragma unroll
    for (int o = 16; o > 0; o >>= 1) v += __shfl_down_sync(0xffffffffu, v, o);
    if (lane == 0) sh[wid] = v;
    __syncthreads();
    if (wid == 0) {
        v = (lane < (blockDim.x >> 5)) ? sh[lane] : 0.f;
#pragma unroll
        for (int o = 4; o > 0; o >>= 1) v += __shfl_down_sync(0xffffffffu, v, o);
    }
    return v;  // valid in thread 0
}

// ---------------- small vector kernels ----------------
__global__ void k_init(float4* __restrict__ b4, float4* __restrict__ ap4) {
    int i = blockIdx.x * blockDim.x + threadIdx.x;
    float4 z = make_float4(0.f, 0.f, 0.f, 0.f);
    if (i < VOL / 4) { b4[i] = z; ap4[i] = z; }
    if (i < 32) g_scal[i] = 0.f;
}

__global__ void k_rp0(float4* __restrict__ r4, float4* __restrict__ p4,
                      const float4* __restrict__ b4, float4* __restrict__ ap4) {
    int i = blockIdx.x * blockDim.x + threadIdx.x;
    float s = 0.f;
    if (i < VOL / 4) {
        float4 b = b4[i], a = ap4[i];
        float4 v = make_float4(b.x - a.x, b.y - a.y, b.z - a.z, b.w - a.w);
        r4[i] = v; p4[i] = v;
        ap4[i] = make_float4(0.f, 0.f, 0.f, 0.f);
        s = v.x * v.x + v.y * v.y + v.z * v.z + v.w * v.w;
    }
    s = block_sum(s);
    if (threadIdx.x == 0) atomicAdd(&g_scal[SC_RR + 0], s);
}

__global__ void k_xr(const float4* __restrict__ xin4, float4* __restrict__ xout4,
                     float4* __restrict__ r4, const float4* __restrict__ p4,
                     const float4* __restrict__ ap4, int it) {
    int i = blockIdx.x * blockDim.x + threadIdx.x;
    float s = 0.f;
    if (i < VOL / 4) {
        float a = g_scal[SC_RR + it] / g_scal[SC_PAP + it];
        float4 x = xin4[i], p = p4[i], ap = ap4[i], r = r4[i];
        x.x = fmaf(a, p.x, x.x); x.y = fmaf(a, p.y, x.y);
        x.z = fmaf(a, p.z, x.z); x.w = fmaf(a, p.w, x.w);
        r.x = fmaf(-a, ap.x, r.x); r.y = fmaf(-a, ap.y, r.y);
        r.z = fmaf(-a, ap.z, r.z); r.w = fmaf(-a, ap.w, r.w);
        xout4[i] = x; r4[i] = r;
        s = r.x * r.x + r.y * r.y + r.z * r.z + r.w * r.w;
    }
    s = block_sum(s);
    if (threadIdx.x == 0) atomicAdd(&g_scal[SC_RR + it + 1], s);
}

__global__ void k_updp(float4* __restrict__ p4, const float4* __restrict__ r4,
                       float4* __restrict__ ap4, int it) {
    int i = blockIdx.x * blockDim.x + threadIdx.x;
    if (i < VOL / 4) {
        float b = g_scal[SC_RR + it + 1] / g_scal[SC_RR + it];
        float4 p = p4[i], r = r4[i];
        p.x = fmaf(b, p.x, r.x); p.y = fmaf(b, p.y, r.y);
        p.z = fmaf(b, p.z, r.z); p.w = fmaf(b, p.w, r.w);
        p4[i] = p;
        ap4[i] = make_float4(0.f, 0.f, 0.f, 0.f);
    }
}

__global__ void k_relu(float4* __restrict__ o4, const float4* __restrict__ x4) {
    int i = blockIdx.x * blockDim.x + threadIdx.x;
    if (i < VOL / 4) {
        float4 x = x4[i];
        o4[i] = make_float4(fmaxf(x.x, 0.f), fmaxf(x.y, 0.f),
                            fmaxf(x.z, 0.f), fmaxf(x.w, 0.f));
    }
}

// ---------------- gathers ----------------
__device__ __forceinline__ float tri_gather_safe(const float* __restrict__ vol,
                                                 float x, float y, float z) {
    float x0f = floorf(x), y0f = floorf(y), z0f = floorf(z);
    float fx = x - x0f, fy = y - y0f, fz = z - z0f;
    int x0 = (int)x0f, y0 = (int)y0f, z0 = (int)z0f;
    float v = 0.f;
#pragma unroll
    for (int dz = 0; dz < 2; dz++) {
        int zi = z0 + dz;
        if (zi < 0 || zi >= DD) continue;
        float wz = dz ? fz : 1.f - fz;
#pragma unroll
        for (int dy = 0; dy < 2; dy++) {
            int yi = y0 + dy;
            if (yi < 0 || yi >= DD) continue;
            float wzy = wz * (dy ? fy : 1.f - fy);
            int base = (zi << 14) + (yi << 7);
#pragma unroll
            for (int dx = 0; dx < 2; dx++) {
                int xi = x0 + dx;
                if (xi < 0 || xi >= DD) continue;
                v = fmaf(wzy * (dx ? fx : 1.f - fx), __ldg(vol + base + xi), v);
            }
        }
    }
    return v;
}

__device__ __forceinline__ float tri_gather_fast(const float* __restrict__ vol,
                                                 float x, float y, float z) {
    float x0f = floorf(x), y0f = floorf(y), z0f = floorf(z);
    float fx = x - x0f, fy = y - y0f, fz = z - z0f;
    int idx = (((int)z0f) << 14) + (((int)y0f) << 7) + (int)x0f;
    const float* p = vol + idx;
    float v000 = __ldg(p),         v001 = __ldg(p + 1);
    float v010 = __ldg(p + 128),   v011 = __ldg(p + 129);
    float v100 = __ldg(p + 16384), v101 = __ldg(p + 16385);
    float v110 = __ldg(p + 16512), v111 = __ldg(p + 16513);
    float c00 = fmaf(fx, v001 - v000, v000);
    float c01 = fmaf(fx, v011 - v010, v010);
    float c10 = fmaf(fx, v101 - v100, v100);
    float c11 = fmaf(fx, v111 - v110, v110);
    float c0 = fmaf(fy, c01 - c00, c00);
    float c1 = fmaf(fy, c11 - c10, c10);
    return fmaf(fz, c1 - c0, c0);
}

// direct global-atomic scatter (boundary / fallback)
__device__ __forceinline__ void tri_scatter_safe(float* __restrict__ vol,
                                                 float x, float y, float z, float wv) {
    float x0f = floorf(x), y0f = floorf(y), z0f = floorf(z);
    float fx = x - x0f, fy = y - y0f, fz = z - z0f;
    int x0 = (int)x0f, y0 = (int)y0f, z0 = (int)z0f;
#pragma unroll
    for (int dz = 0; dz < 2; dz++) {
        int zi = z0 + dz;
        if (zi < 0 || zi >= DD) continue;
        float wz = (dz ? fz : 1.f - fz) * wv;
#pragma unroll
        for (int dy = 0; dy < 2; dy++) {
            int yi = y0 + dy;
            if (yi < 0 || yi >= DD) continue;
            float wzy = wz * (dy ? fy : 1.f - fy);
            int base = (zi << 14) + (yi << 7);
#pragma unroll
            for (int dx = 0; dx < 2; dx++) {
                int xi = x0 + dx;
                if (xi < 0 || xi >= DD) continue;
                atomicAdd(vol + base + xi, wzy * (dx ? fx : 1.f - fx));
            }
        }
    }
}

// private-SMEM scatter: one tap's 8 corners into thread-private 5^3 tile
__device__ __forceinline__ void tri_scatter_priv(float* __restrict__ priv,
                                                 int ox, int oy, int oz,
                                                 float x, float y, float z, float wv) {
    float x0f = floorf(x), y0f = floorf(y), z0f = floorf(z);
    float fx = x - x0f, fy = y - y0f, fz = z - z0f;
    int c = (((int)z0f - oz) * 5 + ((int)y0f - oy)) * 5 + ((int)x0f - ox);
    float wz1 = fz * wv, wz0 = wv - wz1;
    float w01 = fy * wz0, w00 = wz0 - w01;
    float w11 = fy * wz1, w10 = wz1 - w11;
    float t;
    t = fx * w00; priv[c * TPB]        += w00 - t; priv[(c + 1) * TPB]  += t;
    t = fx * w01; priv[(c + 5) * TPB]  += w01 - t; priv[(c + 6) * TPB]  += t;
    t = fx * w10; priv[(c + 25) * TPB] += w10 - t; priv[(c + 26) * TPB] += t;
    t = fx * w11; priv[(c + 30) * TPB] += w11 - t; priv[(c + 31) * TPB] += t;
}

// ---------------- geometry ----------------
struct Geo {
    float qx, qy, qz;
    float rx, ry, rz;
    int status;  // 0 reject, 1 interior fast, 2 boundary slow, 3 fallback
};

__device__ __forceinline__ Geo pixel_geo(const float* sT, int w, int h) {
    Geo g;
    float u = (w - 63.5f) * 1.5f;
    float v = (h - 63.5f) * 1.5f;
    g.qx = sT[0] * u + sT[1] * v + sT[3]  + 63.5f;
    g.qy = sT[4] * u + sT[5] * v + sT[7]  + 63.5f;
    g.qz = sT[8] * u + sT[9] * v + sT[11] + 63.5f;
    g.rx = fabsf(sT[0]) + fabsf(sT[1]) + fabsf(sT[2]);
    g.ry = fabsf(sT[4]) + fabsf(sT[5]) + fabsf(sT[6]);
    g.rz = fabsf(sT[8]) + fabsf(sT[9]) + fabsf(sT[10]);
    bool rej = (g.qx + g.rx < -1.f) | (g.qx - g.rx >= 128.f) |
               (g.qy + g.ry < -1.f) | (g.qy - g.ry >= 128.f) |
               (g.qz + g.rz < -1.f) | (g.qz - g.rz >= 128.f);
    bool inter = (g.qx - g.rx >= 0.f) & (g.qx + g.rx < 127.f) &
                 (g.qy - g.ry >= 0.f) & (g.qy + g.ry < 127.f) &
                 (g.qz - g.rz >= 0.f) & (g.qz + g.rz < 127.f);
    bool fits = (g.rx < 1.49f) & (g.ry < 1.49f) & (g.rz < 1.49f);
    g.status = rej ? 0 : (fits ? (inter ? 1 : 2) : 3);
    return g;
}

// flush private tile to global with bounds check, skipping zeros
__device__ __forceinline__ void flush_priv(const float* __restrict__ priv,
                                           float* __restrict__ dst,
                                           int ox, int oy, int oz) {
#pragma unroll 5
    for (int c = 0; c < PCELLS; c++) {
        float v = priv[c * TPB];
        if (v != 0.f) {
            int x = ox + (c % 5), y = oy + ((c / 5) % 5), z = oz + (c / 25);
            if ((unsigned)x < DD && (unsigned)y < DD && (unsigned)z < DD)
                atomicAdd(dst + (z << 14) + (y << 7) + x, v);
        }
    }
}

// ---------------- fused AtA ----------------
__global__ void __launch_bounds__(TPB)
k_AtA(const float* __restrict__ th, const float* __restrict__ src,
      const float* __restrict__ psf, float* __restrict__ dst,
      float* __restrict__ pap) {
    extern __shared__ float scr[];
    __shared__ float sp[27];
    __shared__ float sT[12];
    int tid = threadIdx.x;
    int b = blockIdx.x;
    int n = b >> 8;                      // 256 blocks per slice
    if (tid < 27) sp[tid] = psf[tid];
    if (tid < 12) sT[tid] = th[n * 12 + tid];
    __syncthreads();
    int tile = b & 255;                  // 16x16 tiles of 8x8 px
    int w = ((tile & 15) << 3) + (tid & 7);
    int h = ((tile >> 4) << 3) + (tid >> 3);

    float r00 = sT[0], r01 = sT[1], r02 = sT[2];
    float r10 = sT[4], r11 = sT[5], r12 = sT[6];
    float r20 = sT[8], r21 = sT[9], r22 = sT[10];
    Geo g = pixel_geo(sT, w, h);

    float acc = 0.f;
    if (g.status == 1) {
        int k = 0;
#pragma unroll
        for (int iz = -1; iz <= 1; iz++) {
            float zx = g.qx + iz * r02, zy = g.qy + iz * r12, zz = g.qz + iz * r22;
#pragma unroll
            for (int iy = -1; iy <= 1; iy++) {
                float yx = zx + iy * r01, yy = zy + iy * r11, yz = zz + iy * r21;
#pragma unroll
                for (int ix = -1; ix <= 1; ix++, k++)
                    acc = fmaf(sp[k], tri_gather_fast(src, yx + ix * r00,
                                                      yy + ix * r10, yz + ix * r20), acc);
            }
        }
    } else if (g.status >= 2) {
        int k = 0;
#pragma unroll
        for (int iz = -1; iz <= 1; iz++) {
            float zx = g.qx + iz * r02, zy = g.qy + iz * r12, zz = g.qz + iz * r22;
#pragma unroll
            for (int iy = -1; iy <= 1; iy++) {
                float yx = zx + iy * r01, yy = zy + iy * r11, yz = zz + iy * r21;
#pragma unroll
                for (int ix = -1; ix <= 1; ix++, k++)
                    acc = fmaf(sp[k], tri_gather_safe(src, yx + ix * r00,
                                                      yy + ix * r10, yz + ix * r20), acc);
            }
        }
    }
    float s = block_sum(acc * acc);
    if (tid == 0) atomicAdd(pap, s);

    if (acc == 0.f) return;
    if (g.status == 3) {   // ultra-safe fallback (never expected)
        int k = 0;
        for (int iz = -1; iz <= 1; iz++) {
            float zx = g.qx + iz * r02, zy = g.qy + iz * r12, zz = g.qz + iz * r22;
            for (int iy = -1; iy <= 1; iy++) {
                float yx = zx + iy * r01, yy = zy + iy * r11, yz = zz + iy * r21;
                for (int ix = -1; ix <= 1; ix++, k++)
                    tri_scatter_safe(dst, yx + ix * r00, yy + ix * r10,
                                     yz + ix * r20, acc * sp[k]);
            }
        }
        return;
    }
    float* priv = scr + tid;
#pragma unroll 5
    for (int c = 0; c < PCELLS; c++) priv[c * TPB] = 0.f;
    int ox = (int)floorf(g.qx - g.rx);
    int oy = (int)floorf(g.qy - g.ry);
    int oz = (int)floorf(g.qz - g.rz);
    int k = 0;
#pragma unroll
    for (int iz = -1; iz <= 1; iz++) {
        float zx = g.qx + iz * r02, zy = g.qy + iz * r12, zz = g.qz + iz * r22;
#pragma unroll
        for (int iy = -1; iy <= 1; iy++) {
            float yx = zx + iy * r01, yy = zy + iy * r11, yz = zz + iy * r21;
#pragma unroll
            for (int ix = -1; ix <= 1; ix++, k++)
                tri_scatter_priv(priv, ox, oy, oz, yx + ix * r00,
                                 yy + ix * r10, yz + ix * r20, acc * sp[k]);
        }
    }
    flush_priv(priv, dst, ox, oy, oz);
}

// ---------------- standalone At (b = At slices) ----------------
__global__ void __launch_bounds__(TPB)
k_At(const float* __restrict__ th, const float* __restrict__ sl,
     const float* __restrict__ psf, float* __restrict__ dst) {
    extern __shared__ float scr[];
    __shared__ float sp[27];
    __shared__ float sT[12];
    int tid = threadIdx.x;
    int b = blockIdx.x;
    int n = b >> 8;
    if (tid < 27) sp[tid] = psf[tid];
    if (tid < 12) sT[tid] = th[n * 12 + tid];
    __syncthreads();
    int tile = b & 255;
    int w = ((tile & 15) << 3) + (tid & 7);
    int h = ((tile >> 4) << 3) + (tid >> 3);

    float r00 = sT[0], r01 = sT[1], r02 = sT[2];
    float r10 = sT[4], r11 = sT[5], r12 = sT[6];
    float r20 = sT[8], r21 = sT[9], r22 = sT[10];
    Geo g = pixel_geo(sT, w, h);
    if (g.status == 0) return;
    float s = __ldg(sl + (n << 14) + (h << 7) + w);
    if (s == 0.f) return;
    if (g.status == 3) {
        int k = 0;
        for (int iz = -1; iz <= 1; iz++) {
            float zx = g.qx + iz * r02, zy = g.qy + iz * r12, zz = g.qz + iz * r22;
            for (int iy = -1; iy <= 1; iy++) {
                float yx = zx + iy * r01, yy = zy + iy * r11, yz = zz + iy * r21;
                for (int ix = -1; ix <= 1; ix++, k++)
                    tri_scatter_safe(dst, yx + ix * r00, yy + ix * r10,
                                     yz + ix * r20, s * sp[k]);
            }
        }
        return;
    }
    float* priv = scr + tid;
#pragma unroll 5
    for (int c = 0; c < PCELLS; c++) priv[c * TPB] = 0.f;
    int ox = (int)floorf(g.qx - g.rx);
    int oy = (int)floorf(g.qy - g.ry);
    int oz = (int)floorf(g.qz - g.rz);
    int k = 0;
#pragma unroll
    for (int iz = -1; iz <= 1; iz++) {
        float zx = g.qx + iz * r02, zy = g.qy + iz * r12, zz = g.qz + iz * r22;
#pragma unroll
        for (int iy = -1; iy <= 1; iy++) {
            float yx = zx + iy * r01, yy = zy + iy * r11, yz = zz + iy * r21;
#pragma unroll
            for (int ix = -1; ix <= 1; ix++, k++)
                tri_scatter_priv(priv, ox, oy, oz, yx + ix * r00,
                                 yy + ix * r10, yz + ix * r20, s * sp[k]);
        }
    }
    flush_priv(priv, dst, ox, oy, oz);
}

// ---------------- host driver ----------------
extern "C" void kernel_launch(void* const* d_in, const int* in_sizes, int n_in,
                              void* d_out, int out_size) {
    const float *theta = nullptr, *slices = nullptr, *vol0 = nullptr, *psf = nullptr;
    for (int i = 0; i < n_in; i++) {
        switch (in_sizes[i]) {
            case 192:   theta  = (const float*)d_in[i]; break;
            case NPIX:  slices = (const float*)d_in[i]; break;
            case VOL:   vol0   = (const float*)d_in[i]; break;
            case 27:    psf    = (const float*)d_in[i]; break;
        }
    }

    float *px, *pr, *pp, *pap, *pb, *pscal;
    cudaGetSymbolAddress((void**)&px,    g_x);
    cudaGetSymbolAddress((void**)&pr,    g_r);
    cudaGetSymbolAddress((void**)&pp,    g_p);
    cudaGetSymbolAddress((void**)&pap,   g_Ap);
    cudaGetSymbolAddress((void**)&pb,    g_b);
    cudaGetSymbolAddress((void**)&pscal, g_scal);

    cudaFuncSetAttribute(k_AtA, cudaFuncAttributeMaxDynamicSharedMemorySize, HEAVY_SMEM);
    cudaFuncSetAttribute(k_At,  cudaFuncAttributeMaxDynamicSharedMemorySize, HEAVY_SMEM);

    const int V4B = (VOL / 4) / 256;   // 2048
    const int PB  = NPIX / TPB;        // 4096 pixel blocks (8x8 tiles)

    // launch #1: no-op so ncu (-s 5 -c 1) lands on the first in-loop k_AtA
    k_nop<<<1, 32>>>();
    k_init<<<V4B, 256>>>((float4*)pb, (float4*)pap);
    k_At<<<PB, TPB, HEAVY_SMEM>>>(theta, slices, psf, pb);
    k_AtA<<<PB, TPB, HEAVY_SMEM>>>(theta, vol0, psf, pap, pscal + SC_DUMP);
    k_rp0<<<V4B, 256>>>((float4*)pr, (float4*)pp, (float4*)pb, (float4*)pap);

    for (int it = 0; it < CG_ITER; it++) {
        k_AtA<<<PB, TPB, HEAVY_SMEM>>>(theta, pp, psf, pap, pscal + SC_PAP + it);
        const float* xin = (it == 0) ? vol0 : px;
        k_xr<<<V4B, 256>>>((const float4*)xin, (float4*)px, (float4*)pr,
                           (const float4*)pp, (const float4*)pap, it);
        k_updp<<<V4B, 256>>>((float4*)pp, (const float4*)pr, (float4*)pap, it);
    }

    k_relu<<<V4B, 256>>>((float4*)d_out, (const float4*)px);
    (void)out_size;
}

// round 13
// speedup vs baseline: 1.4909x; 1.0112x over previous
#include <cuda_runtime.h>
#include <math.h>

#define DD 128
#define VOL (DD*DD*DD)
#define NSL 16
#define NPIX (NSL*DD*DD)
#define CG_ITER 10

#define SC_RR   0
#define SC_PAP  16
#define SC_DUMP 31

#define TPB 128            // 16x8 pixel tile per block
#define PCX 5
#define PCY 5
#define PCZ 4
#define PCELLS (PCX*PCY*PCZ)            // 100
#define HEAVY_SMEM (PCELLS * TPB * 4)   // 51200 B -> 4 CTAs/SM = 16 warps

__device__ float g_x[VOL];
__device__ float g_r[VOL];
__device__ float g_p[VOL];
__device__ float g_Ap[VOL];
__device__ float g_b[VOL];
__device__ float g_scal[32];

__global__ void k_nop() {}

// ---------------- block reduction (sum) ----------------
__device__ __forceinline__ float block_sum(float v) {
    __shared__ float sh[8];
    int lane = threadIdx.x & 31, wid = threadIdx.x >> 5;
#pragma unroll
    for (int o = 16; o > 0; o >>= 1) v += __shfl_down_sync(0xffffffffu, v, o);
    if (lane == 0) sh[wid] = v;
    __syncthreads();
    if (wid == 0) {
        v = (lane < (blockDim.x >> 5)) ? sh[lane] : 0.f;
#pragma unroll
        for (int o = 4; o > 0; o >>= 1) v += __shfl_down_sync(0xffffffffu, v, o);
    }
    return v;
}

// ---------------- small vector kernels ----------------
__global__ void k_init(float4* __restrict__ b4, float4* __restrict__ ap4) {
    int i = blockIdx.x * blockDim.x + threadIdx.x;
    float4 z = make_float4(0.f, 0.f, 0.f, 0.f);
    if (i < VOL / 4) { b4[i] = z; ap4[i] = z; }
    if (i < 32) g_scal[i] = 0.f;
}

__global__ void k_rp0(float4* __restrict__ r4, float4* __restrict__ p4,
                      const float4* __restrict__ b4, float4* __restrict__ ap4) {
    int i = blockIdx.x * blockDim.x + threadIdx.x;
    float s = 0.f;
    if (i < VOL / 4) {
        float4 b = b4[i], a = ap4[i];
        float4 v = make_float4(b.x - a.x, b.y - a.y, b.z - a.z, b.w - a.w);
        r4[i] = v; p4[i] = v;
        ap4[i] = make_float4(0.f, 0.f, 0.f, 0.f);
        s = v.x * v.x + v.y * v.y + v.z * v.z + v.w * v.w;
    }
    s = block_sum(s);
    if (threadIdx.x == 0) atomicAdd(&g_scal[SC_RR + 0], s);
}

__global__ void k_xr(const float4* __restrict__ xin4, float4* __restrict__ xout4,
                     float4* __restrict__ r4, const float4* __restrict__ p4,
                     const float4* __restrict__ ap4, int it) {
    int i = blockIdx.x * blockDim.x + threadIdx.x;
    float s = 0.f;
    if (i < VOL / 4) {
        float a = g_scal[SC_RR + it] / g_scal[SC_PAP + it];
        float4 x = xin4[i], p = p4[i], ap = ap4[i], r = r4[i];
        x.x = fmaf(a, p.x, x.x); x.y = fmaf(a, p.y, x.y);
        x.z = fmaf(a, p.z, x.z); x.w = fmaf(a, p.w, x.w);
        r.x = fmaf(-a, ap.x, r.x); r.y = fmaf(-a, ap.y, r.y);
        r.z = fmaf(-a, ap.z, r.z); r.w = fmaf(-a, ap.w, r.w);
        xout4[i] = x; r4[i] = r;
        s = r.x * r.x + r.y * r.y + r.z * r.z + r.w * r.w;
    }
    s = block_sum(s);
    if (threadIdx.x == 0) atomicAdd(&g_scal[SC_RR + it + 1], s);
}

__global__ void k_updp(float4* __restrict__ p4, const float4* __restrict__ r4,
                       float4* __restrict__ ap4, int it) {
    int i = blockIdx.x * blockDim.x + threadIdx.x;
    if (i < VOL / 4) {
        float b = g_scal[SC_RR + it + 1] / g_scal[SC_RR + it];
        float4 p = p4[i], r = r4[i];
        p.x = fmaf(b, p.x, r.x); p.y = fmaf(b, p.y, r.y);
        p.z = fmaf(b, p.z, r.z); p.w = fmaf(b, p.w, r.w);
        p4[i] = p;
        ap4[i] = make_float4(0.f, 0.f, 0.f, 0.f);
    }
}

__global__ void k_relu(float4* __restrict__ o4, const float4* __restrict__ x4) {
    int i = blockIdx.x * blockDim.x + threadIdx.x;
    if (i < VOL / 4) {
        float4 x = x4[i];
        o4[i] = make_float4(fmaxf(x.x, 0.f), fmaxf(x.y, 0.f),
                            fmaxf(x.z, 0.f), fmaxf(x.w, 0.f));
    }
}

// ---------------- gathers ----------------
__device__ __forceinline__ float tri_gather_safe(const float* __restrict__ vol,
                                                 float x, float y, float z) {
    float x0f = floorf(x), y0f = floorf(y), z0f = floorf(z);
    float fx = x - x0f, fy = y - y0f, fz = z - z0f;
    int x0 = (int)x0f, y0 = (int)y0f, z0 = (int)z0f;
    float v = 0.f;
#pragma unroll
    for (int dz = 0; dz < 2; dz++) {
        int zi = z0 + dz;
        if (zi < 0 || zi >= DD) continue;
        float wz = dz ? fz : 1.f - fz;
#pragma unroll
        for (int dy = 0; dy < 2; dy++) {
            int yi = y0 + dy;
            if (yi < 0 || yi >= DD) continue;
            float wzy = wz * (dy ? fy : 1.f - fy);
            int base = (zi << 14) + (yi << 7);
#pragma unroll
            for (int dx = 0; dx < 2; dx++) {
                int xi = x0 + dx;
                if (xi < 0 || xi >= DD) continue;
                v = fmaf(wzy * (dx ? fx : 1.f - fx), __ldg(vol + base + xi), v);
            }
        }
    }
    return v;
}

__device__ __forceinline__ float tri_gather_fast(const float* __restrict__ vol,
                                                 float x, float y, float z) {
    float x0f = floorf(x), y0f = floorf(y), z0f = floorf(z);
    float fx = x - x0f, fy = y - y0f, fz = z - z0f;
    int idx = (((int)z0f) << 14) + (((int)y0f) << 7) + (int)x0f;
    const float* p = vol + idx;
    float v000 = __ldg(p),         v001 = __ldg(p + 1);
    float v010 = __ldg(p + 128),   v011 = __ldg(p + 129);
    float v100 = __ldg(p + 16384), v101 = __ldg(p + 16385);
    float v110 = __ldg(p + 16512), v111 = __ldg(p + 16513);
    float c00 = fmaf(fx, v001 - v000, v000);
    float c01 = fmaf(fx, v011 - v010, v010);
    float c10 = fmaf(fx, v101 - v100, v100);
    float c11 = fmaf(fx, v111 - v110, v110);
    float c0 = fmaf(fy, c01 - c00, c00);
    float c1 = fmaf(fy, c11 - c10, c10);
    return fmaf(fz, c1 - c0, c0);
}

// direct global-atomic scatter (boundary / fallback)
__device__ __forceinline__ void tri_scatter_safe(float* __restrict__ vol,
                                                 float x, float y, float z, float wv) {
    float x0f = floorf(x), y0f = floorf(y), z0f = floorf(z);
    float fx = x - x0f, fy = y - y0f, fz = z - z0f;
    int x0 = (int)x0f, y0 = (int)y0f, z0 = (int)z0f;
#pragma unroll
    for (int dz = 0; dz < 2; dz++) {
        int zi = z0 + dz;
        if (zi < 0 || zi >= DD) continue;
        float wz = (dz ? fz : 1.f - fz) * wv;
#pragma unroll
        for (int dy = 0; dy < 2; dy++) {
            int yi = y0 + dy;
            if (yi < 0 || yi >= DD) continue;
            float wzy = wz * (dy ? fy : 1.f - fy);
            int base = (zi << 14) + (yi << 7);
#pragma unroll
            for (int dx = 0; dx < 2; dx++) {
                int xi = x0 + dx;
                if (xi < 0 || xi >= DD) continue;
                atomicAdd(vol + base + xi, wzy * (dx ? fx : 1.f - fx));
            }
        }
    }
}

// private-SMEM scatter: 5x5x4 z-window; z-overflow taps go straight to global
// (interior pixels only -> global addresses guaranteed in-bounds)
__device__ __forceinline__ void tri_scatter_priv(float* __restrict__ priv,
                                                 float* __restrict__ dst,
                                                 int ox, int oy, int oz,
                                                 float x, float y, float z, float wv) {
    float x0f = floorf(x), y0f = floorf(y), z0f = floorf(z);
    float fx = x - x0f, fy = y - y0f, fz = z - z0f;
    int x0 = (int)x0f, y0 = (int)y0f, z0 = (int)z0f;
    int cz = z0 - oz;
    float wz1 = fz * wv, wz0 = wv - wz1;
    float w01 = fy * wz0, w00 = wz0 - w01;
    float w11 = fy * wz1, w10 = wz1 - w11;
    float t00 = fx * w00, s00 = w00 - t00;
    float t01 = fx * w01, s01 = w01 - t01;
    float t10 = fx * w10, s10 = w10 - t10;
    float t11 = fx * w11, s11 = w11 - t11;
    int cb = (cz * PCY + (y0 - oy)) * PCX + (x0 - ox);
    if (cz <= PCZ - 2) {               // common: both z-planes in window
        priv[cb * TPB]                    += s00;
        priv[(cb + 1) * TPB]              += t00;
        priv[(cb + PCX) * TPB]            += s01;
        priv[(cb + PCX + 1) * TPB]        += t01;
        priv[(cb + PCX*PCY) * TPB]        += s10;
        priv[(cb + PCX*PCY + 1) * TPB]    += t10;
        priv[(cb + PCX*PCY + PCX) * TPB]      += s11;
        priv[(cb + PCX*PCY + PCX + 1) * TPB]  += t11;
    } else {
        int gi = (z0 << 14) + (y0 << 7) + x0;
        if (cz == PCZ - 1) {           // lower plane in window, upper overflows
            priv[cb * TPB]             += s00;
            priv[(cb + 1) * TPB]       += t00;
            priv[(cb + PCX) * TPB]     += s01;
            priv[(cb + PCX + 1) * TPB] += t01;
        } else {                        // cz == PCZ: both planes overflow
            atomicAdd(dst + gi,       s00);
            atomicAdd(dst + gi + 1,   t00);
            atomicAdd(dst + gi + 128, s01);
            atomicAdd(dst + gi + 129, t01);
        }
        atomicAdd(dst + gi + 16384, s10);
        atomicAdd(dst + gi + 16385, t10);
        atomicAdd(dst + gi + 16512, s11);
        atomicAdd(dst + gi + 16513, t11);
    }
}

// ---------------- geometry ----------------
struct Geo {
    float qx, qy, qz;
    float rx, ry, rz;
    int status;  // 0 reject, 1 interior fast, 2 boundary slow, 3 fallback
};

__device__ __forceinline__ Geo pixel_geo(const float* sT, int w, int h) {
    Geo g;
    float u = (w - 63.5f) * 1.5f;
    float v = (h - 63.5f) * 1.5f;
    g.qx = sT[0] * u + sT[1] * v + sT[3]  + 63.5f;
    g.qy = sT[4] * u + sT[5] * v + sT[7]  + 63.5f;
    g.qz = sT[8] * u + sT[9] * v + sT[11] + 63.5f;
    g.rx = fabsf(sT[0]) + fabsf(sT[1]) + fabsf(sT[2]);
    g.ry = fabsf(sT[4]) + fabsf(sT[5]) + fabsf(sT[6]);
    g.rz = fabsf(sT[8]) + fabsf(sT[9]) + fabsf(sT[10]);
    bool rej = (g.qx + g.rx < -1.f) | (g.qx - g.rx >= 128.f) |
               (g.qy + g.ry < -1.f) | (g.qy - g.ry >= 128.f) |
               (g.qz + g.rz < -1.f) | (g.qz - g.rz >= 128.f);
    bool inter = (g.qx - g.rx >= 0.f) & (g.qx + g.rx < 127.f) &
                 (g.qy - g.ry >= 0.f) & (g.qy + g.ry < 127.f) &
                 (g.qz - g.rz >= 0.f) & (g.qz + g.rz < 127.f);
    bool fits = (g.rx < 1.49f) & (g.ry < 1.49f) & (g.rz < 1.49f);
    g.status = rej ? 0 : (fits ? (inter ? 1 : 2) : 3);
    return g;
}

// zero + flush: fully unrolled, compile-time incremental addressing, no div/mod
__device__ __forceinline__ void zero_priv(float* __restrict__ priv) {
#pragma unroll
    for (int c = 0; c < PCELLS; c++) priv[c * TPB] = 0.f;
}

__device__ __forceinline__ void flush_priv(const float* __restrict__ priv,
                                           float* __restrict__ dst,
                                           int ox, int oy, int oz) {
    int gb = (oz << 14) + (oy << 7) + ox;
#pragma unroll
    for (int cz = 0; cz < PCZ; cz++) {
#pragma unroll
        for (int cy = 0; cy < PCY; cy++) {
#pragma unroll
            for (int cx = 0; cx < PCX; cx++) {
                float v = priv[((cz * PCY + cy) * PCX + cx) * TPB];
                if (v != 0.f)
                    atomicAdd(dst + gb + (cz << 14) + (cy << 7) + cx, v);
            }
        }
    }
}

// ---------------- fused AtA ----------------
__global__ void __launch_bounds__(TPB)
k_AtA(const float* __restrict__ th, const float* __restrict__ src,
      const float* __restrict__ psf, float* __restrict__ dst,
      float* __restrict__ pap) {
    extern __shared__ float scr[];
    __shared__ float sp[27];
    __shared__ float sT[12];
    int tid = threadIdx.x;
    int b = blockIdx.x;
    int n = b >> 7;                      // 128 blocks per slice
    if (tid < 27) sp[tid] = psf[tid];
    if (tid < 12) sT[tid] = th[n * 12 + tid];
    __syncthreads();
    int tile = b & 127;                  // 8 x-tiles * 16 y-tiles of 16x8 px
    int w = ((tile & 7) << 4) + (tid & 15);
    int h = ((tile >> 3) << 3) + (tid >> 4);

    float r00 = sT[0], r01 = sT[1], r02 = sT[2];
    float r10 = sT[4], r11 = sT[5], r12 = sT[6];
    float r20 = sT[8], r21 = sT[9], r22 = sT[10];
    Geo g = pixel_geo(sT, w, h);

    float acc = 0.f;
    if (g.status == 1) {
        int k = 0;
#pragma unroll
        for (int iz = -1; iz <= 1; iz++) {
            float zx = g.qx + iz * r02, zy = g.qy + iz * r12, zz = g.qz + iz * r22;
#pragma unroll
            for (int iy = -1; iy <= 1; iy++) {
                float yx = zx + iy * r01, yy = zy + iy * r11, yz = zz + iy * r21;
#pragma unroll
                for (int ix = -1; ix <= 1; ix++, k++)
                    acc = fmaf(sp[k], tri_gather_fast(src, yx + ix * r00,
                                                      yy + ix * r10, yz + ix * r20), acc);
            }
        }
    } else if (g.status >= 2) {
        int k = 0;
#pragma unroll
        for (int iz = -1; iz <= 1; iz++) {
            float zx = g.qx + iz * r02, zy = g.qy + iz * r12, zz = g.qz + iz * r22;
#pragma unroll
            for (int iy = -1; iy <= 1; iy++) {
                float yx = zx + iy * r01, yy = zy + iy * r11, yz = zz + iy * r21;
#pragma unroll
                for (int ix = -1; ix <= 1; ix++, k++)
                    acc = fmaf(sp[k], tri_gather_safe(src, yx + ix * r00,
                                                      yy + ix * r10, yz + ix * r20), acc);
            }
        }
    }
    float s = block_sum(acc * acc);
    if (tid == 0) atomicAdd(pap, s);

    if (acc == 0.f) return;
    if (g.status >= 2) {   // boundary or fallback: direct global atomics
        int k = 0;
        for (int iz = -1; iz <= 1; iz++) {
            float zx = g.qx + iz * r02, zy = g.qy + iz * r12, zz = g.qz + iz * r22;
            for (int iy = -1; iy <= 1; iy++) {
                float yx = zx + iy * r01, yy = zy + iy * r11, yz = zz + iy * r21;
                for (int ix = -1; ix <= 1; ix++, k++)
                    tri_scatter_safe(dst, yx + ix * r00, yy + ix * r10,
                                     yz + ix * r20, acc * sp[k]);
            }
        }
        return;
    }
    float* priv = scr + tid;
    zero_priv(priv);
    int ox = (int)floorf(g.qx - g.rx);
    int oy = (int)floorf(g.qy - g.ry);
    int oz = (int)floorf(g.qz - g.rz);
    int k = 0;
#pragma unroll
    for (int iz = -1; iz <= 1; iz++) {
        float zx = g.qx + iz * r02, zy = g.qy + iz * r12, zz = g.qz + iz * r22;
#pragma unroll
        for (int iy = -1; iy <= 1; iy++) {
            float yx = zx + iy * r01, yy = zy + iy * r11, yz = zz + iy * r21;
#pragma unroll
            for (int ix = -1; ix <= 1; ix++, k++)
                tri_scatter_priv(priv, dst, ox, oy, oz, yx + ix * r00,
                                 yy + ix * r10, yz + ix * r20, acc * sp[k]);
        }
    }
    flush_priv(priv, dst, ox, oy, oz);
}

// ---------------- standalone At (b = At slices) ----------------
__global__ void __launch_bounds__(TPB)
k_At(const float* __restrict__ th, const float* __restrict__ sl,
     const float* __restrict__ psf, float* __restrict__ dst) {
    extern __shared__ float scr[];
    __shared__ float sp[27];
    __shared__ float sT[12];
    int tid = threadIdx.x;
    int b = blockIdx.x;
    int n = b >> 7;
    if (tid < 27) sp[tid] = psf[tid];
    if (tid < 12) sT[tid] = th[n * 12 + tid];
    __syncthreads();
    int tile = b & 127;
    int w = ((tile & 7) << 4) + (tid & 15);
    int h = ((tile >> 3) << 3) + (tid >> 4);

    float r00 = sT[0], r01 = sT[1], r02 = sT[2];
    float r10 = sT[4], r11 = sT[5], r12 = sT[6];
    float r20 = sT[8], r21 = sT[9], r22 = sT[10];
    Geo g = pixel_geo(sT, w, h);
    if (g.status == 0) return;
    float s = __ldg(sl + (n << 14) + (h << 7) + w);
    if (s == 0.f) return;
    if (g.status >= 2) {
        int k = 0;
        for (int iz = -1; iz <= 1; iz++) {
            float zx = g.qx + iz * r02, zy = g.qy + iz * r12, zz = g.qz + iz * r22;
            for (int iy = -1; iy <= 1; iy++) {
                float yx = zx + iy * r01, yy = zy + iy * r11, yz = zz + iy * r21;
                for (int ix = -1; ix <= 1; ix++, k++)
                    tri_scatter_safe(dst, yx + ix * r00, yy + ix * r10,
                                     yz + ix * r20, s * sp[k]);
            }
        }
        return;
    }
    float* priv = scr + tid;
    zero_priv(priv);
    int ox = (int)floorf(g.qx - g.rx);
    int oy = (int)floorf(g.qy - g.ry);
    int oz = (int)floorf(g.qz - g.rz);
    int k = 0;
#pragma unroll
    for (int iz = -1; iz <= 1; iz++) {
        float zx = g.qx + iz * r02, zy = g.qy + iz * r12, zz = g.qz + iz * r22;
#pragma unroll
        for (int iy = -1; iy <= 1; iy++) {
            float yx = zx + iy * r01, yy = zy + iy * r11, yz = zz + iy * r21;
#pragma unroll
            for (int ix = -1; ix <= 1; ix++, k++)
                tri_scatter_priv(priv, dst, ox, oy, oz, yx + ix * r00,
                                 yy + ix * r10, yz + ix * r20, s * sp[k]);
        }
    }
    flush_priv(priv, dst, ox, oy, oz);
}

// ---------------- host driver ----------------
extern "C" void kernel_launch(void* const* d_in, const int* in_sizes, int n_in,
                              void* d_out, int out_size) {
    const float *theta = nullptr, *slices = nullptr, *vol0 = nullptr, *psf = nullptr;
    for (int i = 0; i < n_in; i++) {
        switch (in_sizes[i]) {
            case 192:   theta  = (const float*)d_in[i]; break;
            case NPIX:  slices = (const float*)d_in[i]; break;
            case VOL:   vol0   = (const float*)d_in[i]; break;
            case 27:    psf    = (const float*)d_in[i]; break;
        }
    }

    float *px, *pr, *pp, *pap, *pb, *pscal;
    cudaGetSymbolAddress((void**)&px,    g_x);
    cudaGetSymbolAddress((void**)&pr,    g_r);
    cudaGetSymbolAddress((void**)&pp,    g_p);
    cudaGetSymbolAddress((void**)&pap,   g_Ap);
    cudaGetSymbolAddress((void**)&pb,    g_b);
    cudaGetSymbolAddress((void**)&pscal, g_scal);

    cudaFuncSetAttribute(k_AtA, cudaFuncAttributeMaxDynamicSharedMemorySize, HEAVY_SMEM);
    cudaFuncSetAttribute(k_At,  cudaFuncAttributeMaxDynamicSharedMemorySize, HEAVY_SMEM);

    const int V4B = (VOL / 4) / 256;   // 2048
    const int PB  = NPIX / TPB;        // 2048 pixel blocks (16x8 tiles)

    // launch #1: no-op so ncu (-s 5 -c 1) lands on the first in-loop k_AtA
    k_nop<<<1, 32>>>();
    k_init<<<V4B, 256>>>((float4*)pb, (float4*)pap);
    k_At<<<PB, TPB, HEAVY_SMEM>>>(theta, slices, psf, pb);
    k_AtA<<<PB, TPB, HEAVY_SMEM>>>(theta, vol0, psf, pap, pscal + SC_DUMP);
    k_rp0<<<V4B, 256>>>((float4*)pr, (float4*)pp, (float4*)pb, (float4*)pap);

    for (int it = 0; it < CG_ITER; it++) {
        k_AtA<<<PB, TPB, HEAVY_SMEM>>>(theta, pp, psf, pap, pscal + SC_PAP + it);
        const float* xin = (it == 0) ? vol0 : px;
        k_xr<<<V4B, 256>>>((const float4*)xin, (float4*)px, (float4*)pr,
                           (const float4*)pp, (const float4*)pap, it);
        k_updp<<<V4B, 256>>>((float4*)pp, (const float4*)pr, (float4*)pap, it);
    }

    k_relu<<<V4B, 256>>>((float4*)d_out, (const float4*)px);
    (void)out_size;
}